// round 2
// baseline (speedup 1.0000x reference)
#include <cuda_runtime.h>

typedef unsigned long long ull_t;

#define BATCH_ 128
#define TLEN 256
#define HID 2048
#define FOURH 8192
#define NSTEP 255
#define BK 16

// Persistent LSTM state (no cudaMalloc allowed).
__device__ float g_h[2][BATCH_ * HID];
__device__ float g_c[BATCH_ * HID];

__device__ __forceinline__ ull_t pack2(float v) {
    ull_t r;
    asm("mov.b64 %0, {%1, %1};" : "=l"(r) : "f"(v));
    return r;
}

__device__ __forceinline__ void fma2(ull_t& d, ull_t a, ull_t b) {
    asm("fma.rn.f32x2 %0, %1, %2, %0;" : "+l"(d) : "l"(a), "l"(b));
}

__device__ __forceinline__ float sigmoidf_(float v) {
    return 1.0f / (1.0f + __expf(-v));
}

__global__ void init_kernel() {
    const int n = BATCH_ * HID;
    for (int i = blockIdx.x * blockDim.x + threadIdx.x; i < n;
         i += gridDim.x * blockDim.x) {
        g_h[0][i] = 0.0f;
        g_c[i] = 0.0f;
    }
}

// One LSTM timestep, fused: z = h@Wh (+x_t*Wx + b), gate activations, c/h update.
// Grid: 128 CTAs, each owns a 16-wide slice of H (so 64 gate columns: g,i,f,o blocks).
// Block: 128 threads, thread tile 8 rows x 8 gate-cols, f32x2 packed accumulators.
__global__ __launch_bounds__(128, 1) void step_kernel(
    const float* __restrict__ x, const float* __restrict__ Wx,
    const float* __restrict__ Wh, const float* __restrict__ bvec, int t)
{
    __shared__ __align__(16) float As[BK][BATCH_];  // [kk][row]  (h tile, transposed)
    __shared__ __align__(16) float Bs[BK][64];      // [kk][gatecol] (Wh tile)
    __shared__ float zs[BATCH_][65];                // padded z tile for epilogue

    const int tid = threadIdx.x;
    const int jb = blockIdx.x * 16;                 // H-column base of this CTA
    const float* __restrict__ h_in = g_h[t & 1];
    float* __restrict__ h_out = g_h[(t + 1) & 1];

    // B-tile (Wh) global-load mapping: thread -> (kk, 8 consecutive gate-cols)
    const int kk_b = tid >> 3;                      // 0..15
    const int cg   = tid & 7;                       // 0..7
    const long bcol = (long)(cg >> 1) * HID + jb + (cg & 1) * 8;

    const int trow = tid >> 3;                      // 0..15 -> rows trow*8..+7
    const int tcol = tid & 7;                       // 0..7  -> cols tcol*8..+7

    ull_t acc[4][8];
    #pragma unroll
    for (int i = 0; i < 4; i++)
        #pragma unroll
        for (int j = 0; j < 8; j++) acc[i][j] = 0ULL;   // (0.f,0.f)

    float4 areg[4];
    float4 breg[2];

    // Prologue: load k0=0 tiles to registers, then SMEM.
    {
        const float* ap = h_in + (long)tid * HID;
        #pragma unroll
        for (int i = 0; i < 4; i++) areg[i] = *(const float4*)(ap + i * 4);
        const float* wp = Wh + (long)kk_b * FOURH + bcol;
        breg[0] = *(const float4*)(wp);
        breg[1] = *(const float4*)(wp + 4);
    }
    #pragma unroll
    for (int i = 0; i < 4; i++) {
        As[i * 4 + 0][tid] = areg[i].x;
        As[i * 4 + 1][tid] = areg[i].y;
        As[i * 4 + 2][tid] = areg[i].z;
        As[i * 4 + 3][tid] = areg[i].w;
    }
    *(float4*)&Bs[kk_b][cg * 8]     = breg[0];
    *(float4*)&Bs[kk_b][cg * 8 + 4] = breg[1];
    __syncthreads();

    #pragma unroll 1
    for (int k0 = 0; k0 < HID; k0 += BK) {
        const bool has_next = (k0 + BK) < HID;
        if (has_next) {
            // Register prefetch of next tiles (hides L2 latency behind compute).
            const float* ap = h_in + (long)tid * HID + k0 + BK;
            #pragma unroll
            for (int i = 0; i < 4; i++) areg[i] = *(const float4*)(ap + i * 4);
            const float* wp = Wh + (long)(k0 + BK + kk_b) * FOURH + bcol;
            breg[0] = *(const float4*)(wp);
            breg[1] = *(const float4*)(wp + 4);
        }
        #pragma unroll
        for (int kk = 0; kk < BK; kk++) {
            ulonglong2 a01 = *(const ulonglong2*)&As[kk][trow * 8];
            ulonglong2 a23 = *(const ulonglong2*)&As[kk][trow * 8 + 4];
            float4 b0 = *(const float4*)&Bs[kk][tcol * 8];
            float4 b1 = *(const float4*)&Bs[kk][tcol * 8 + 4];
            ull_t av0 = a01.x, av1 = a01.y, av2 = a23.x, av3 = a23.y;
            ull_t bv[8];
            bv[0] = pack2(b0.x); bv[1] = pack2(b0.y);
            bv[2] = pack2(b0.z); bv[3] = pack2(b0.w);
            bv[4] = pack2(b1.x); bv[5] = pack2(b1.y);
            bv[6] = pack2(b1.z); bv[7] = pack2(b1.w);
            #pragma unroll
            for (int j = 0; j < 8; j++) {
                fma2(acc[0][j], av0, bv[j]);
                fma2(acc[1][j], av1, bv[j]);
                fma2(acc[2][j], av2, bv[j]);
                fma2(acc[3][j], av3, bv[j]);
            }
        }
        __syncthreads();
        if (has_next) {
            #pragma unroll
            for (int i = 0; i < 4; i++) {
                As[i * 4 + 0][tid] = areg[i].x;
                As[i * 4 + 1][tid] = areg[i].y;
                As[i * 4 + 2][tid] = areg[i].z;
                As[i * 4 + 3][tid] = areg[i].w;
            }
            *(float4*)&Bs[kk_b][cg * 8]     = breg[0];
            *(float4*)&Bs[kk_b][cg * 8 + 4] = breg[1];
        }
        __syncthreads();
    }

    // Spill z tile to SMEM so each thread can see all 4 gates of a column.
    #pragma unroll
    for (int i = 0; i < 4; i++) {
        #pragma unroll
        for (int j = 0; j < 8; j++) {
            float2 v = *reinterpret_cast<float2*>(&acc[i][j]);
            const int r = trow * 8 + 2 * i;
            const int c = tcol * 8 + j;
            zs[r][c] = v.x;
            zs[r + 1][c] = v.y;
        }
    }
    __syncthreads();

    // LSTM update: thread handles one H-column q for 16 rows (coalesced writes).
    {
        const int q = tid & 15;
        const int rbase = (tid >> 4) * 16;
        const int hcol = jb + q;
        const float wxg = Wx[hcol],           bg = bvec[hcol];
        const float wxi = Wx[HID + hcol],     bi = bvec[HID + hcol];
        const float wxf = Wx[2 * HID + hcol], bf = bvec[2 * HID + hcol];
        const float wxo = Wx[3 * HID + hcol], bo = bvec[3 * HID + hcol];
        #pragma unroll 4
        for (int rr = 0; rr < 16; rr++) {
            const int row = rbase + rr;
            const float xt = x[row * TLEN + t];
            const float zg = zs[row][q]      + xt * wxg + bg;
            const float zi = zs[row][16 + q] + xt * wxi + bi;
            const float zf = zs[row][32 + q] + xt * wxf + bf;
            const float zo = zs[row][48 + q] + xt * wxo + bo;
            const float gg = tanhf(zg);
            const float ii = sigmoidf_(zi);
            const float ff = sigmoidf_(zf);
            const float oo = sigmoidf_(zo);
            const long idx = (long)row * HID + hcol;
            const float cn = gg * ii + g_c[idx] * ff;
            g_c[idx] = cn;
            h_out[idx] = tanhf(cn) * oo;
        }
    }
}

// Final projection + softmax: one warp per batch row; lanes 0..9 own classes.
__global__ void proj_kernel(const float* __restrict__ Wph,
                            const float* __restrict__ bp,
                            float* __restrict__ out)
{
    const int row = blockIdx.x;
    const int lane = threadIdx.x;
    const float* __restrict__ h = g_h[NSTEP & 1] + (long)row * HID;

    float acc = -1e30f;
    if (lane < 10) {
        acc = bp[lane];
        #pragma unroll 8
        for (int k = 0; k < HID; k++)
            acc += h[k] * Wph[k * 10 + lane];
    }
    float m = acc;
    #pragma unroll
    for (int off = 16; off > 0; off >>= 1)
        m = fmaxf(m, __shfl_xor_sync(0xffffffffu, m, off));
    float e = (lane < 10) ? __expf(acc - m) : 0.0f;
    float s = e;
    #pragma unroll
    for (int off = 16; off > 0; off >>= 1)
        s += __shfl_xor_sync(0xffffffffu, s, off);
    if (lane < 10) out[row * 10 + lane] = e / s;
}

extern "C" void kernel_launch(void* const* d_in, const int* in_sizes, int n_in,
                              void* d_out, int out_size) {
    (void)in_sizes; (void)n_in; (void)out_size;
    const float* x   = (const float*)d_in[0];
    const float* Wx  = (const float*)d_in[1];
    const float* Wh  = (const float*)d_in[2];
    const float* b   = (const float*)d_in[3];
    const float* Wph = (const float*)d_in[4];
    const float* bp  = (const float*)d_in[5];
    float* out = (float*)d_out;

    init_kernel<<<128, 256>>>();
    for (int t = 0; t < NSTEP; t++) {
        step_kernel<<<FOURH / 64, 128>>>(x, Wx, Wh, b, t);
    }
    proj_kernel<<<BATCH_, 32>>>(Wph, bp, out);
}

// round 3
// speedup vs baseline: 1.0261x; 1.0261x over previous
#include <cuda_runtime.h>

typedef unsigned long long ull_t;

#define BATCH_ 128
#define TLEN 256
#define HID 2048
#define FOURH 8192
#define NSTEP 255
#define BK 16

// Persistent LSTM state (no cudaMalloc allowed).
__device__ float g_h[2][BATCH_ * HID];
__device__ float g_c[BATCH_ * HID];

__device__ __forceinline__ ull_t pack2(float v) {
    ull_t r;
    asm("mov.b64 %0, {%1, %1};" : "=l"(r) : "f"(v));
    return r;
}

__device__ __forceinline__ void fma2(ull_t& d, ull_t a, ull_t b) {
    asm("fma.rn.f32x2 %0, %1, %2, %0;" : "+l"(d) : "l"(a), "l"(b));
}

__device__ __forceinline__ float sigmoidf_(float v) {
    return 1.0f / (1.0f + __expf(-v));
}

__global__ void init_kernel() {
    const int n = BATCH_ * HID;
    for (int i = blockIdx.x * blockDim.x + threadIdx.x; i < n;
         i += gridDim.x * blockDim.x) {
        g_h[0][i] = 0.0f;
        g_c[i] = 0.0f;
    }
}

// One LSTM timestep, fused: z = h@Wh (+x_t*Wx + b), gates, c/h update.
// Grid: 128 CTAs, each owns 16 H-cols (64 gate cols).
// Block: 256 threads = 2 teams of 128; each team computes the full 128x64 tile
// over one half of K (intra-CTA K-split) -> 8 warps/SM for latency hiding.
// SMEM tiles are overlaid with the z-combine buffer (union) to stay <48KB.
__global__ __launch_bounds__(256, 1) void step_kernel(
    const float* __restrict__ x, const float* __restrict__ Wx,
    const float* __restrict__ Wh, const float* __restrict__ bvec, int t)
{
    // Layout: [0 .. 2*BK*128) A tiles (team0, team1)
    //         [4096 .. 4096+2*BK*64) B tiles
    //         overlay: zs[128][65] from offset 0 (8320 floats total)
    __shared__ __align__(16) float smem[8320];

    const int tid  = threadIdx.x;
    const int team = tid >> 7;          // 0 or 1
    const int ttid = tid & 127;

    float (*As)[128] = reinterpret_cast<float(*)[128]>(&smem[team * (BK * 128)]);
    float (*Bs)[64]  = reinterpret_cast<float(*)[64]>(&smem[2 * BK * 128 + team * (BK * 64)]);

    const int jb = blockIdx.x * 16;     // H-column base of this CTA
    const float* __restrict__ h_in = g_h[t & 1];
    float* __restrict__ h_out = g_h[(t + 1) & 1];

    // B-tile (Wh) global-load mapping: thread -> (kk, 8 consecutive gate-cols)
    const int kk_b = ttid >> 3;         // 0..15
    const int cg   = ttid & 7;          // 0..7
    const long bcol = (long)(cg >> 1) * HID + jb + (cg & 1) * 8;

    const int trow = ttid >> 3;         // 0..15 -> rows trow*8..+7
    const int tcol = ttid & 7;          // 0..7  -> cols tcol*8..+7

    const int kbeg = team * (HID / 2);
    const int kend = kbeg + HID / 2;

    ull_t acc[4][8];
    #pragma unroll
    for (int i = 0; i < 4; i++)
        #pragma unroll
        for (int j = 0; j < 8; j++) acc[i][j] = 0ULL;   // (0.f, 0.f)

    float4 areg[4];
    float4 breg[2];

    // Prologue: load first tiles of this team's K-range.
    {
        const float* ap = h_in + (long)ttid * HID + kbeg;
        #pragma unroll
        for (int i = 0; i < 4; i++) areg[i] = *(const float4*)(ap + i * 4);
        const float* wp = Wh + (long)(kbeg + kk_b) * FOURH + bcol;
        breg[0] = *(const float4*)(wp);
        breg[1] = *(const float4*)(wp + 4);
    }
    #pragma unroll
    for (int i = 0; i < 4; i++) {
        As[i * 4 + 0][ttid] = areg[i].x;
        As[i * 4 + 1][ttid] = areg[i].y;
        As[i * 4 + 2][ttid] = areg[i].z;
        As[i * 4 + 3][ttid] = areg[i].w;
    }
    *(float4*)&Bs[kk_b][cg * 8]     = breg[0];
    *(float4*)&Bs[kk_b][cg * 8 + 4] = breg[1];
    __syncthreads();

    #pragma unroll 1
    for (int k0 = kbeg; k0 < kend; k0 += BK) {
        const bool has_next = (k0 + BK) < kend;
        if (has_next) {
            // Register prefetch of next tiles (hides L2 latency behind compute).
            const float* ap = h_in + (long)ttid * HID + k0 + BK;
            #pragma unroll
            for (int i = 0; i < 4; i++) areg[i] = *(const float4*)(ap + i * 4);
            const float* wp = Wh + (long)(k0 + BK + kk_b) * FOURH + bcol;
            breg[0] = *(const float4*)(wp);
            breg[1] = *(const float4*)(wp + 4);
        }
        #pragma unroll
        for (int kk = 0; kk < BK; kk++) {
            ulonglong2 a01 = *(const ulonglong2*)&As[kk][trow * 8];
            ulonglong2 a23 = *(const ulonglong2*)&As[kk][trow * 8 + 4];
            float4 b0 = *(const float4*)&Bs[kk][tcol * 8];
            float4 b1 = *(const float4*)&Bs[kk][tcol * 8 + 4];
            ull_t av0 = a01.x, av1 = a01.y, av2 = a23.x, av3 = a23.y;
            ull_t bv[8];
            bv[0] = pack2(b0.x); bv[1] = pack2(b0.y);
            bv[2] = pack2(b0.z); bv[3] = pack2(b0.w);
            bv[4] = pack2(b1.x); bv[5] = pack2(b1.y);
            bv[6] = pack2(b1.z); bv[7] = pack2(b1.w);
            #pragma unroll
            for (int j = 0; j < 8; j++) {
                fma2(acc[0][j], av0, bv[j]);
                fma2(acc[1][j], av1, bv[j]);
                fma2(acc[2][j], av2, bv[j]);
                fma2(acc[3][j], av3, bv[j]);
            }
        }
        __syncthreads();
        if (has_next) {
            #pragma unroll
            for (int i = 0; i < 4; i++) {
                As[i * 4 + 0][ttid] = areg[i].x;
                As[i * 4 + 1][ttid] = areg[i].y;
                As[i * 4 + 2][ttid] = areg[i].z;
                As[i * 4 + 3][ttid] = areg[i].w;
            }
            *(float4*)&Bs[kk_b][cg * 8]     = breg[0];
            *(float4*)&Bs[kk_b][cg * 8 + 4] = breg[1];
        }
        __syncthreads();
    }

    // Tiles are dead; overlay z-buffer. Combine the two K-half partials.
    float (*zs)[65] = reinterpret_cast<float(*)[65]>(smem);

    if (team == 0) {
        #pragma unroll
        for (int i = 0; i < 4; i++) {
            #pragma unroll
            for (int j = 0; j < 8; j++) {
                float2 v = *reinterpret_cast<float2*>(&acc[i][j]);
                const int r = trow * 8 + 2 * i;
                const int c = tcol * 8 + j;
                zs[r][c]     = v.x;
                zs[r + 1][c] = v.y;
            }
        }
    }
    __syncthreads();
    if (team == 1) {
        #pragma unroll
        for (int i = 0; i < 4; i++) {
            #pragma unroll
            for (int j = 0; j < 8; j++) {
                float2 v = *reinterpret_cast<float2*>(&acc[i][j]);
                const int r = trow * 8 + 2 * i;
                const int c = tcol * 8 + j;
                zs[r][c]     += v.x;
                zs[r + 1][c] += v.y;
            }
        }
    }
    __syncthreads();

    // LSTM update: 256 threads; thread handles one H-column q for 8 rows.
    {
        const int q = tid & 15;
        const int rbase = (tid >> 4) * 8;
        const int hcol = jb + q;
        const float wxg = Wx[hcol],           bg = bvec[hcol];
        const float wxi = Wx[HID + hcol],     bi = bvec[HID + hcol];
        const float wxf = Wx[2 * HID + hcol], bf = bvec[2 * HID + hcol];
        const float wxo = Wx[3 * HID + hcol], bo = bvec[3 * HID + hcol];
        #pragma unroll 4
        for (int rr = 0; rr < 8; rr++) {
            const int row = rbase + rr;
            const float xt = x[row * TLEN + t];
            const float zg = zs[row][q]      + xt * wxg + bg;
            const float zi = zs[row][16 + q] + xt * wxi + bi;
            const float zf = zs[row][32 + q] + xt * wxf + bf;
            const float zo = zs[row][48 + q] + xt * wxo + bo;
            const float gg = tanhf(zg);
            const float ii = sigmoidf_(zi);
            const float ff = sigmoidf_(zf);
            const float oo = sigmoidf_(zo);
            const long idx = (long)row * HID + hcol;
            const float cn = gg * ii + g_c[idx] * ff;
            g_c[idx] = cn;
            h_out[idx] = tanhf(cn) * oo;
        }
    }
}

// Final projection + softmax: one warp per batch row; lanes 0..9 own classes.
__global__ void proj_kernel(const float* __restrict__ Wph,
                            const float* __restrict__ bp,
                            float* __restrict__ out)
{
    const int row = blockIdx.x;
    const int lane = threadIdx.x;
    const float* __restrict__ h = g_h[NSTEP & 1] + (long)row * HID;

    float acc = -1e30f;
    if (lane < 10) {
        acc = bp[lane];
        #pragma unroll 8
        for (int k = 0; k < HID; k++)
            acc += h[k] * Wph[k * 10 + lane];
    }
    float m = acc;
    #pragma unroll
    for (int off = 16; off > 0; off >>= 1)
        m = fmaxf(m, __shfl_xor_sync(0xffffffffu, m, off));
    float e = (lane < 10) ? __expf(acc - m) : 0.0f;
    float s = e;
    #pragma unroll
    for (int off = 16; off > 0; off >>= 1)
        s += __shfl_xor_sync(0xffffffffu, s, off);
    if (lane < 10) out[row * 10 + lane] = e / s;
}

extern "C" void kernel_launch(void* const* d_in, const int* in_sizes, int n_in,
                              void* d_out, int out_size) {
    (void)in_sizes; (void)n_in; (void)out_size;
    const float* x   = (const float*)d_in[0];
    const float* Wx  = (const float*)d_in[1];
    const float* Wh  = (const float*)d_in[2];
    const float* b   = (const float*)d_in[3];
    const float* Wph = (const float*)d_in[4];
    const float* bp  = (const float*)d_in[5];
    float* out = (float*)d_out;

    init_kernel<<<128, 256>>>();
    for (int t = 0; t < NSTEP; t++) {
        step_kernel<<<FOURH / 64, 256>>>(x, Wx, Wh, b, t);
    }
    proj_kernel<<<BATCH_, 32>>>(Wph, bp, out);
}

// round 5
// speedup vs baseline: 3.2501x; 3.1673x over previous
#include <cuda_runtime.h>
#include <cuda_fp16.h>
#include <cstdint>

#define BATCH_ 128
#define TLEN   256
#define HID    2048
#define FOURH  8192
#define NSTEP  255
#define BK     64
#define NCHUNK 32          // HID / BK
#define NBLK   128         // CTAs; each owns 64 permuted gate cols = 16 H cols

// ---------------- persistent device state (no cudaMalloc allowed) -----------
__device__ float g_c[BATCH_ * HID];
__device__ __half g_h_hi[2][BATCH_ * HID];   // h split-fp16, double-buffered
__device__ __half g_h_lo[2][BATCH_ * HID];
// Wh^T, gate-permuted, split-fp16: row col' = blk*64 + gate*16 + q, cols = k
__device__ __half g_W_hi[(size_t)FOURH * HID];
__device__ __half g_W_lo[(size_t)FOURH * HID];

// ---------------- helpers (all sm_80+ base-target PTX) ----------------------
__device__ __forceinline__ uint32_t sw128(uint32_t x) { return x ^ ((x >> 3) & 0x70); }

__device__ __forceinline__ uint32_t smem_u32(const void* p) {
    uint32_t a;
    asm("{ .reg .u64 t; cvta.to.shared.u64 t, %1; cvt.u32.u64 %0, t; }"
        : "=r"(a) : "l"(p));
    return a;
}

__device__ __forceinline__ void cp16(uint32_t d, const void* s) {
    asm volatile("cp.async.cg.shared.global [%0], [%1], 16;"
                 :: "r"(d), "l"(s) : "memory");
}

__device__ __forceinline__ void ldsm4(uint32_t* r, uint32_t a) {
    asm volatile("ldmatrix.sync.aligned.m8n8.x4.shared.b16 {%0,%1,%2,%3}, [%4];"
                 : "=r"(r[0]), "=r"(r[1]), "=r"(r[2]), "=r"(r[3]) : "r"(a));
}

__device__ __forceinline__ void mma16816(float* c, const uint32_t* a,
                                         uint32_t b0, uint32_t b1) {
    asm volatile(
        "mma.sync.aligned.m16n8k16.row.col.f32.f16.f16.f32 "
        "{%0,%1,%2,%3}, {%4,%5,%6,%7}, {%8,%9}, {%0,%1,%2,%3};"
        : "+f"(c[0]), "+f"(c[1]), "+f"(c[2]), "+f"(c[3])
        : "r"(a[0]), "r"(a[1]), "r"(a[2]), "r"(a[3]), "r"(b0), "r"(b1));
}

__device__ __forceinline__ float fast_sigmoid(float v) {
    return __fdividef(1.0f, 1.0f + __expf(-v));
}
__device__ __forceinline__ float fast_tanh(float v) {
    float a = fabsf(v);
    float t = __expf(-2.0f * a);
    float r = __fdividef(1.0f - t, 1.0f + t);
    return copysignf(r, v);
}

// smem byte offsets (dynamic smem, double-buffered stages of 48KB)
#define AHI_O 0
#define ALO_O 16384
#define BHI_O 32768
#define BLO_O 40960
#define STAGE_B 49152
#define SMEM_TOTAL (2 * STAGE_B)   // 98304

// ---------------- init: zero state + build permuted split-fp16 Wh^T ---------
__global__ void init_kernel(const float* __restrict__ Wh) {
    const long total = (long)FOURH * HID;   // 16,777,216
    for (long e = blockIdx.x * (long)blockDim.x + threadIdx.x; e < total;
         e += (long)gridDim.x * blockDim.x) {
        const int colp = (int)(e / HID);    // permuted column index
        const int k    = (int)(e % HID);
        const int blk  = colp >> 6;
        const int r    = colp & 63;
        const int gate = r >> 4;
        const int q    = r & 15;
        const int o    = gate * HID + blk * 16 + q;   // original gate column
        const float v  = Wh[(size_t)k * FOURH + o];
        const __half hi = __float2half(v);
        const __half lo = __float2half(v - __half2float(hi));
        g_W_hi[e] = hi;
        g_W_lo[e] = lo;
        if (e < BATCH_ * HID) {
            g_c[e] = 0.0f;
            g_h_hi[0][e] = __float2half(0.0f);
            g_h_lo[0][e] = __float2half(0.0f);
        }
    }
}

// ---------------- load one K-chunk into a smem stage -------------------------
__device__ __forceinline__ void issue_chunk(uint32_t sb, int tid, int blk, int c,
                                            const __half* __restrict__ Ah,
                                            const __half* __restrict__ Al) {
    const int k0 = c * BK;
    #pragma unroll
    for (int i = 0; i < 4; i++) {                 // A: 128 rows x 64 k, hi+lo
        const int idx = tid + i * 256;
        const int row = idx >> 3;
        const int kk  = (idx & 7) * 8;
        const uint32_t so = sw128((uint32_t)row * 128 + kk * 2);
        const size_t go = (size_t)row * HID + k0 + kk;
        cp16(sb + AHI_O + so, Ah + go);
        cp16(sb + ALO_O + so, Al + go);
    }
    #pragma unroll
    for (int i = 0; i < 2; i++) {                 // B: 64 rows x 64 k, hi+lo
        const int idx = tid + i * 256;
        const int n  = idx >> 3;
        const int kk = (idx & 7) * 8;
        const uint32_t so = sw128((uint32_t)n * 128 + kk * 2);
        const size_t go = (size_t)(blk * 64 + n) * HID + k0 + kk;
        cp16(sb + BHI_O + so, g_W_hi + go);
        cp16(sb + BLO_O + so, g_W_lo + go);
    }
    asm volatile("cp.async.commit_group;" ::: "memory");
}

// ---------------- one LSTM timestep ------------------------------------------
__global__ __launch_bounds__(256, 1) void step_kernel(
    const float* __restrict__ x, const float* __restrict__ Wx,
    const float* __restrict__ bvec, int t)
{
    extern __shared__ __align__(1024) unsigned char smem[];
    const uint32_t sb = smem_u32(smem);
    const int tid  = threadIdx.x;
    const int w    = tid >> 5;
    const int lane = tid & 31;
    const int blk  = blockIdx.x;

    const int par0 = t & 1;
    const int par1 = (t + 1) & 1;
    const __half* __restrict__ Ah = g_h_hi[par0];
    const __half* __restrict__ Al = g_h_lo[par0];

    float cacc[8][4];
    #pragma unroll
    for (int j = 0; j < 8; j++)
        #pragma unroll
        for (int i = 0; i < 4; i++) cacc[j][i] = 0.0f;

    // prologue: chunk 0 into stage 0
    issue_chunk(sb, tid, blk, 0, Ah, Al);

    const int lm = lane & 15;         // ldmatrix row selector
    const int lh = lane >> 4;         // k-half selector

    #pragma unroll 1
    for (int c = 0; c < NCHUNK; c++) {
        if (c + 1 < NCHUNK)
            issue_chunk(sb + ((c + 1) & 1) * STAGE_B, tid, blk, c + 1, Ah, Al);
        if (c + 1 < NCHUNK)
            asm volatile("cp.async.wait_group 1;" ::: "memory");
        else
            asm volatile("cp.async.wait_group 0;" ::: "memory");
        __syncthreads();

        const uint32_t st = sb + (c & 1) * STAGE_B;
        #pragma unroll
        for (int ks = 0; ks < 4; ks++) {
            const uint32_t kb = (uint32_t)(ks * 16 + lh * 8) * 2;
            uint32_t ahi[4], alo[4];
            const uint32_t aoff = sw128((uint32_t)(w * 16 + lm) * 128 + kb);
            ldsm4(ahi, st + AHI_O + aoff);
            ldsm4(alo, st + ALO_O + aoff);
            uint32_t bh[16], bl[16];
            #pragma unroll
            for (int jj = 0; jj < 4; jj++) {
                const uint32_t boff = sw128((uint32_t)(jj * 16 + lm) * 128 + kb);
                ldsm4(&bh[jj * 4], st + BHI_O + boff);
                ldsm4(&bl[jj * 4], st + BLO_O + boff);
            }
            #pragma unroll
            for (int j = 0; j < 8; j++) {
                const int jj = j >> 1, pr = j & 1;
                const uint32_t bh0 = bh[jj * 4 + pr], bh1 = bh[jj * 4 + pr + 2];
                const uint32_t bl0 = bl[jj * 4 + pr], bl1 = bl[jj * 4 + pr + 2];
                mma16816(cacc[j], ahi, bh0, bh1);   // hi*hi
                mma16816(cacc[j], ahi, bl0, bl1);   // hi*lo
                mma16816(cacc[j], alo, bh0, bh1);   // lo*hi
            }
        }
        __syncthreads();
    }

    // ---- fused LSTM epilogue: all 4 gates of (row,q) live in this thread ----
    const int r0 = w * 16 + (lane >> 2);
    const int qb = (lane & 3) * 2;
    const float xt0 = x[r0 * TLEN + t];
    const float xt1 = x[(r0 + 8) * TLEN + t];

    #pragma unroll
    for (int qhalf = 0; qhalf < 2; qhalf++) {
        #pragma unroll
        for (int e = 0; e < 2; e++) {
            const int q = qb + qhalf * 8 + e;
            const int hcol = blk * 16 + q;
            const float wxg = Wx[hcol],           bg = bvec[hcol];
            const float wxi = Wx[HID + hcol],     bi = bvec[HID + hcol];
            const float wxf = Wx[2 * HID + hcol], bf = bvec[2 * HID + hcol];
            const float wxo = Wx[3 * HID + hcol], bo = bvec[3 * HID + hcol];
            #pragma unroll
            for (int rhalf = 0; rhalf < 2; rhalf++) {
                const int row = r0 + rhalf * 8;
                const float xt = rhalf ? xt1 : xt0;
                const int ri = rhalf * 2 + e;
                const float zg = cacc[0 + qhalf][ri] + xt * wxg + bg;
                const float zi = cacc[2 + qhalf][ri] + xt * wxi + bi;
                const float zf = cacc[4 + qhalf][ri] + xt * wxf + bf;
                const float zo = cacc[6 + qhalf][ri] + xt * wxo + bo;
                const float gg = fast_tanh(zg);
                const float ii = fast_sigmoid(zi);
                const float ff = fast_sigmoid(zf);
                const float oo = fast_sigmoid(zo);
                const size_t ci = (size_t)row * HID + hcol;
                const float cnew = gg * ii + g_c[ci] * ff;
                g_c[ci] = cnew;
                const float hv = fast_tanh(cnew) * oo;
                const __half hh = __float2half(hv);
                const __half hl = __float2half(hv - __half2float(hh));
                g_h_hi[par1][ci] = hh;
                g_h_lo[par1][ci] = hl;
            }
        }
    }
}

// ---------------- final projection + softmax ---------------------------------
__global__ void proj_kernel(const float* __restrict__ Wph,
                            const float* __restrict__ bp,
                            float* __restrict__ out)
{
    const int row = blockIdx.x;
    const int lane = threadIdx.x;
    const int par = NSTEP & 1;   // 1

    float acc = -1e30f;
    if (lane < 10) {
        acc = bp[lane];
        const size_t base = (size_t)row * HID;
        for (int k = 0; k < HID; k++) {
            const float hv = __half2float(g_h_hi[par][base + k]) +
                             __half2float(g_h_lo[par][base + k]);
            acc += hv * Wph[k * 10 + lane];
        }
    }
    float m = acc;
    #pragma unroll
    for (int off = 16; off > 0; off >>= 1)
        m = fmaxf(m, __shfl_xor_sync(0xffffffffu, m, off));
    float e = (lane < 10) ? __expf(acc - m) : 0.0f;
    float s = e;
    #pragma unroll
    for (int off = 16; off > 0; off >>= 1)
        s += __shfl_xor_sync(0xffffffffu, s, off);
    if (lane < 10) out[row * 10 + lane] = e / s;
}

extern "C" void kernel_launch(void* const* d_in, const int* in_sizes, int n_in,
                              void* d_out, int out_size) {
    (void)in_sizes; (void)n_in; (void)out_size;
    const float* x   = (const float*)d_in[0];
    const float* Wx  = (const float*)d_in[1];
    const float* Wh  = (const float*)d_in[2];
    const float* b   = (const float*)d_in[3];
    const float* Wph = (const float*)d_in[4];
    const float* bp  = (const float*)d_in[5];
    float* out = (float*)d_out;

    static int attr_set = 0;
    if (!attr_set) {
        cudaFuncSetAttribute(step_kernel,
                             cudaFuncAttributeMaxDynamicSharedMemorySize,
                             SMEM_TOTAL);
        attr_set = 1;
    }

    init_kernel<<<4096, 256>>>(Wh);
    for (int t = 0; t < NSTEP; t++) {
        step_kernel<<<NBLK, 256, SMEM_TOTAL>>>(x, Wx, b, t);
    }
    proj_kernel<<<BATCH_, 32>>>(Wph, bp, out);
}

// round 6
// speedup vs baseline: 3.3899x; 1.0430x over previous
#include <cuda_runtime.h>
#include <cuda_fp16.h>
#include <cstdint>

#define BATCH_ 128
#define TLEN   256
#define HID    2048
#define FOURH  8192
#define NSTEP  255
#define BK     64
#define NCHUNK 32          // HID / BK
#define NBLK   128         // CTAs; each owns 64 permuted gate cols = 16 H cols

// ---------------- persistent device state (no cudaMalloc allowed) -----------
__device__ float g_c[BATCH_ * HID];
__device__ __half g_h_hi[2][BATCH_ * HID];   // h split-fp16, double-buffered
__device__ __half g_h_lo[2][BATCH_ * HID];
// Wh^T, gate-permuted, split-fp16: permuted col p = blk*64 + w_n*32 + gate*8 + q
__device__ __half g_W_hi[(size_t)FOURH * HID];
__device__ __half g_W_lo[(size_t)FOURH * HID];

// ---------------- helpers (all sm_80+ base-target PTX) ----------------------
__device__ __forceinline__ uint32_t sw128(uint32_t x) { return x ^ ((x >> 3) & 0x70); }

__device__ __forceinline__ uint32_t smem_u32(const void* p) {
    uint32_t a;
    asm("{ .reg .u64 t; cvta.to.shared.u64 t, %1; cvt.u32.u64 %0, t; }"
        : "=r"(a) : "l"(p));
    return a;
}

__device__ __forceinline__ void cp16(uint32_t d, const void* s) {
    asm volatile("cp.async.cg.shared.global [%0], [%1], 16;"
                 :: "r"(d), "l"(s) : "memory");
}

__device__ __forceinline__ void ldsm4(uint32_t* r, uint32_t a) {
    asm volatile("ldmatrix.sync.aligned.m8n8.x4.shared.b16 {%0,%1,%2,%3}, [%4];"
                 : "=r"(r[0]), "=r"(r[1]), "=r"(r[2]), "=r"(r[3]) : "r"(a));
}

__device__ __forceinline__ void mma16816(float* c, const uint32_t* a,
                                         uint32_t b0, uint32_t b1) {
    asm volatile(
        "mma.sync.aligned.m16n8k16.row.col.f32.f16.f16.f32 "
        "{%0,%1,%2,%3}, {%4,%5,%6,%7}, {%8,%9}, {%0,%1,%2,%3};"
        : "+f"(c[0]), "+f"(c[1]), "+f"(c[2]), "+f"(c[3])
        : "r"(a[0]), "r"(a[1]), "r"(a[2]), "r"(a[3]), "r"(b0), "r"(b1));
}

__device__ __forceinline__ float fast_sigmoid(float v) {
    return __fdividef(1.0f, 1.0f + __expf(-v));
}
__device__ __forceinline__ float fast_tanh(float v) {
    float a = fabsf(v);
    float t = __expf(-2.0f * a);
    float r = __fdividef(1.0f - t, 1.0f + t);
    return copysignf(r, v);
}

// smem stage layout (per 48KB stage): A_hi 16K | A_lo 16K | B_hi 8K | B_lo 8K
#define AHI_O 0
#define ALO_O 16384
#define BHI_O 32768
#define BLO_O 40960
#define STAGE_B 49152
#define NSTAGE 3
#define SMEM_TOTAL (NSTAGE * STAGE_B)   // 147456

// ---------------- init: coalesced tiled transpose of Wh into split fp16 -----
// permuted col p = blk*64 + r, r = w_n*32 + gate*8 + q ; original col
// o = gate*HID + blk*16 + w_n*8 + q
__global__ __launch_bounds__(256) void init_w_kernel(const float* __restrict__ Wh) {
    __shared__ float tile[64][65];
    const int cb = blockIdx.x >> 5;        // 0..127  (colp tile /64)
    const int kb = blockIdx.x & 31;        // 0..31   (k tile /64)
    const int tid = threadIdx.x;

    // load: 64 k x 64 colp, reads of 8 consecutive floats (fully sectored)
    {
        const int k_local = tid >> 2;      // 0..63
        const int seg0 = tid & 3;
        const size_t krow = (size_t)(kb * 64 + k_local) * FOURH;
        #pragma unroll
        for (int ss = 0; ss < 2; ss++) {
            const int s = seg0 + ss * 4;   // 0..7
            const int w_n = s >> 2;
            const int gate = s & 3;
            const int base_o = gate * HID + cb * 16 + w_n * 8;
            const float4 v0 = *(const float4*)(Wh + krow + base_o);
            const float4 v1 = *(const float4*)(Wh + krow + base_o + 4);
            const int r0 = w_n * 32 + gate * 8;
            tile[r0 + 0][k_local] = v0.x;
            tile[r0 + 1][k_local] = v0.y;
            tile[r0 + 2][k_local] = v0.z;
            tile[r0 + 3][k_local] = v0.w;
            tile[r0 + 4][k_local] = v1.x;
            tile[r0 + 5][k_local] = v1.y;
            tile[r0 + 6][k_local] = v1.z;
            tile[r0 + 7][k_local] = v1.w;
        }
    }
    __syncthreads();

    // store: thread -> (r, 16 k), vectorized 2x16B per array
    {
        const int r  = tid >> 2;           // 0..63
        const int k0 = (tid & 3) * 16;
        const size_t obase = (size_t)(cb * 64 + r) * HID + kb * 64 + k0;
        __half hibuf[16], lobuf[16];
        #pragma unroll
        for (int i = 0; i < 16; i++) {
            const float v = tile[r][k0 + i];
            const __half hi = __float2half(v);
            hibuf[i] = hi;
            lobuf[i] = __float2half(v - __half2float(hi));
        }
        *(uint4*)(g_W_hi + obase)     = *(uint4*)(hibuf);
        *(uint4*)(g_W_hi + obase + 8) = *(uint4*)(hibuf + 8);
        *(uint4*)(g_W_lo + obase)     = *(uint4*)(lobuf);
        *(uint4*)(g_W_lo + obase + 8) = *(uint4*)(lobuf + 8);
    }
}

__global__ void zero_kernel() {
    const int n = BATCH_ * HID;
    for (int i = blockIdx.x * blockDim.x + threadIdx.x; i < n;
         i += gridDim.x * blockDim.x) {
        g_c[i] = 0.0f;
        g_h_hi[0][i] = __float2half(0.0f);
        g_h_lo[0][i] = __float2half(0.0f);
    }
}

// ---------------- load one K-chunk into a smem stage -------------------------
__device__ __forceinline__ void issue_chunk(uint32_t st, int tid, int blk, int k0,
                                            const __half* __restrict__ Ah,
                                            const __half* __restrict__ Al) {
    const int arow = tid >> 3;
    const int kk   = (tid & 7) * 8;
    const uint32_t aso = sw128((uint32_t)arow * 128 + kk * 2);
    const size_t ago = (size_t)arow * HID + k0 + kk;
    #pragma unroll
    for (int i = 0; i < 4; i++) {                 // A: 128 rows x 64 k, hi+lo
        cp16(st + AHI_O + aso + i * 4096, Ah + ago + (size_t)i * 32 * HID);
        cp16(st + ALO_O + aso + i * 4096, Al + ago + (size_t)i * 32 * HID);
    }
    const size_t bgo = (size_t)(blk * 64 + arow) * HID + k0 + kk;
    #pragma unroll
    for (int i = 0; i < 2; i++) {                 // B: 64 rows x 64 k, hi+lo
        cp16(st + BHI_O + aso + i * 4096, g_W_hi + bgo + (size_t)i * 32 * HID);
        cp16(st + BLO_O + aso + i * 4096, g_W_lo + bgo + (size_t)i * 32 * HID);
    }
    asm volatile("cp.async.commit_group;" ::: "memory");
}

// ---------------- one LSTM timestep ------------------------------------------
__global__ __launch_bounds__(256, 1) void step_kernel(
    const float* __restrict__ x, const float* __restrict__ Wx,
    const float* __restrict__ bvec, int t)
{
    extern __shared__ __align__(1024) unsigned char smem[];
    const uint32_t sb = smem_u32(smem);
    const int tid  = threadIdx.x;
    const int w    = tid >> 5;
    const int lane = tid & 31;
    const int w_m  = w >> 1;          // 0..3 (row group of 32)
    const int w_n  = w & 1;           // 0..1 (col group of 32)
    const int blk  = blockIdx.x;

    const int par0 = t & 1;
    const int par1 = (t + 1) & 1;
    const __half* __restrict__ Ah = g_h_hi[par0];
    const __half* __restrict__ Al = g_h_lo[par0];

    float cacc[2][4][4];
    #pragma unroll
    for (int m = 0; m < 2; m++)
        #pragma unroll
        for (int g = 0; g < 4; g++)
            #pragma unroll
            for (int i = 0; i < 4; i++) cacc[m][g][i] = 0.0f;

    // prologue: fill 3 stages
    issue_chunk(sb,               tid, blk, 0, Ah, Al);
    issue_chunk(sb + STAGE_B,     tid, blk, BK, Ah, Al);
    issue_chunk(sb + 2 * STAGE_B, tid, blk, 2 * BK, Ah, Al);

    const int lm = lane & 15;
    const int lh = lane >> 4;
    const uint32_t a_row_off = (uint32_t)(w_m * 32 + lm) * 128;
    const uint32_t b_row_off = (uint32_t)(w_n * 32 + lm) * 128;

    uint32_t stage = 0;
    #pragma unroll 1
    for (int c = 0; c < NCHUNK; c++) {
        if (c < NCHUNK - 2)
            asm volatile("cp.async.wait_group 2;" ::: "memory");
        else if (c == NCHUNK - 2)
            asm volatile("cp.async.wait_group 1;" ::: "memory");
        else
            asm volatile("cp.async.wait_group 0;" ::: "memory");
        __syncthreads();

        const uint32_t st = sb + stage * STAGE_B;
        #pragma unroll
        for (int ks = 0; ks < 4; ks++) {
            const uint32_t kb = (uint32_t)(ks * 16 + lh * 8) * 2;
            uint32_t ahi[2][4], alo[2][4], bhi[2][4], blo[2][4];
            #pragma unroll
            for (int m = 0; m < 2; m++) {
                const uint32_t ao = sw128(a_row_off + (uint32_t)m * 2048 + kb);
                ldsm4(ahi[m], st + AHI_O + ao);
                ldsm4(alo[m], st + ALO_O + ao);
            }
            #pragma unroll
            for (int gg = 0; gg < 2; gg++) {
                const uint32_t bo = sw128(b_row_off + (uint32_t)gg * 2048 + kb);
                ldsm4(bhi[gg], st + BHI_O + bo);
                ldsm4(blo[gg], st + BLO_O + bo);
            }
            #pragma unroll
            for (int m = 0; m < 2; m++) {
                #pragma unroll
                for (int g = 0; g < 4; g++) {
                    const int gg = g >> 1, pr = g & 1;
                    const uint32_t b0h = bhi[gg][pr], b1h = bhi[gg][pr + 2];
                    const uint32_t b0l = blo[gg][pr], b1l = blo[gg][pr + 2];
                    mma16816(cacc[m][g], ahi[m], b0h, b1h);   // hi*hi
                    mma16816(cacc[m][g], ahi[m], b0l, b1l);   // hi*lo
                    mma16816(cacc[m][g], alo[m], b0h, b1h);   // lo*hi
                }
            }
        }
        __syncthreads();
        if (c + NSTAGE < NCHUNK)
            issue_chunk(st, tid, blk, (c + NSTAGE) * BK, Ah, Al);
        stage = (stage == NSTAGE - 1) ? 0 : stage + 1;
    }

    // ---- fused LSTM epilogue: all 4 gates of (row, hcol) in this thread ----
    const int q2 = (lane & 3) * 2;
    const int hcol0 = blk * 16 + w_n * 8 + q2;       // even
    float wx[4][2], bb[4][2];
    #pragma unroll
    for (int g = 0; g < 4; g++) {
        const int o = g * HID + hcol0;
        wx[g][0] = Wx[o];     wx[g][1] = Wx[o + 1];
        bb[g][0] = bvec[o];   bb[g][1] = bvec[o + 1];
    }
    const int rbase = w_m * 32 + (lane >> 2);

    #pragma unroll
    for (int m = 0; m < 2; m++) {
        #pragma unroll
        for (int rh = 0; rh < 2; rh++) {
            const int row = rbase + m * 16 + rh * 8;
            const float xt = x[row * TLEN + t];
            const size_t base = (size_t)row * HID + hcol0;
            const float2 cold = *(const float2*)(g_c + base);
            float hv[2], cv[2];
            #pragma unroll
            for (int e = 0; e < 2; e++) {
                const int ri = rh * 2 + e;
                const float zg = cacc[m][0][ri] + xt * wx[0][e] + bb[0][e];
                const float zi = cacc[m][1][ri] + xt * wx[1][e] + bb[1][e];
                const float zf = cacc[m][2][ri] + xt * wx[2][e] + bb[2][e];
                const float zo = cacc[m][3][ri] + xt * wx[3][e] + bb[3][e];
                const float gg = fast_tanh(zg);
                const float ii = fast_sigmoid(zi);
                const float ff = fast_sigmoid(zf);
                const float oo = fast_sigmoid(zo);
                const float co = (e == 0) ? cold.x : cold.y;
                cv[e] = gg * ii + co * ff;
                hv[e] = fast_tanh(cv[e]) * oo;
            }
            *(float2*)(g_c + base) = make_float2(cv[0], cv[1]);
            __half hh0 = __float2half(hv[0]);
            __half hh1 = __float2half(hv[1]);
            __half hl0 = __float2half(hv[0] - __half2float(hh0));
            __half hl1 = __float2half(hv[1] - __half2float(hh1));
            *(__half2*)(g_h_hi[par1] + base) = __halves2half2(hh0, hh1);
            *(__half2*)(g_h_lo[par1] + base) = __halves2half2(hl0, hl1);
        }
    }
}

// ---------------- final projection + softmax ---------------------------------
__global__ void proj_kernel(const float* __restrict__ Wph,
                            const float* __restrict__ bp,
                            float* __restrict__ out)
{
    const int row = blockIdx.x;
    const int lane = threadIdx.x;
    const int par = NSTEP & 1;   // 1

    float acc = -1e30f;
    if (lane < 10) {
        acc = bp[lane];
        const size_t base = (size_t)row * HID;
        for (int k = 0; k < HID; k++) {
            const float hv = __half2float(g_h_hi[par][base + k]) +
                             __half2float(g_h_lo[par][base + k]);
            acc += hv * Wph[k * 10 + lane];
        }
    }
    float m = acc;
    #pragma unroll
    for (int off = 16; off > 0; off >>= 1)
        m = fmaxf(m, __shfl_xor_sync(0xffffffffu, m, off));
    float e = (lane < 10) ? __expf(acc - m) : 0.0f;
    float s = e;
    #pragma unroll
    for (int off = 16; off > 0; off >>= 1)
        s += __shfl_xor_sync(0xffffffffu, s, off);
    if (lane < 10) out[row * 10 + lane] = e / s;
}

extern "C" void kernel_launch(void* const* d_in, const int* in_sizes, int n_in,
                              void* d_out, int out_size) {
    (void)in_sizes; (void)n_in; (void)out_size;
    const float* x   = (const float*)d_in[0];
    const float* Wx  = (const float*)d_in[1];
    const float* Wh  = (const float*)d_in[2];
    const float* b   = (const float*)d_in[3];
    const float* Wph = (const float*)d_in[4];
    const float* bp  = (const float*)d_in[5];
    float* out = (float*)d_out;

    static int attr_set = 0;
    if (!attr_set) {
        cudaFuncSetAttribute(step_kernel,
                             cudaFuncAttributeMaxDynamicSharedMemorySize,
                             SMEM_TOTAL);
        attr_set = 1;
    }

    init_w_kernel<<<4096, 256>>>(Wh);
    zero_kernel<<<256, 256>>>();
    for (int t = 0; t < NSTEP; t++) {
        step_kernel<<<NBLK, 256, SMEM_TOTAL>>>(x, Wx, b, t);
    }
    proj_kernel<<<BATCH_, 32>>>(Wph, bp, out);
}

// round 7
// speedup vs baseline: 3.4204x; 1.0090x over previous
#include <cuda_runtime.h>
#include <cuda_fp16.h>
#include <cstdint>

#define BATCH_ 128
#define TLEN   256
#define HID    2048
#define FOURH  8192
#define NSTEP  255
#define BK     64
#define NCHUNK 32          // HID / BK
#define NBLK   128         // CTAs; each owns 64 permuted gate cols = 16 H cols

// ---------------- persistent device state (no cudaMalloc allowed) -----------
__device__ float g_c[BATCH_ * HID];
__device__ __half g_h_hi[2][BATCH_ * HID];   // h split-fp16, double-buffered
__device__ __half g_h_lo[2][BATCH_ * HID];
// Wh^T, gate-permuted, split-fp16: permuted col p = blk*64 + w_n*32 + gate*8 + q
__device__ __half g_W_hi[(size_t)FOURH * HID];
__device__ __half g_W_lo[(size_t)FOURH * HID];

// ---------------- helpers (all sm_80+ base-target PTX) ----------------------
__device__ __forceinline__ uint32_t sw128(uint32_t x) { return x ^ ((x >> 3) & 0x70); }

__device__ __forceinline__ uint32_t smem_u32(const void* p) {
    uint32_t a;
    asm("{ .reg .u64 t; cvta.to.shared.u64 t, %1; cvt.u32.u64 %0, t; }"
        : "=r"(a) : "l"(p));
    return a;
}

__device__ __forceinline__ void cp16(uint32_t d, const void* s) {
    asm volatile("cp.async.cg.shared.global [%0], [%1], 16;"
                 :: "r"(d), "l"(s) : "memory");
}

__device__ __forceinline__ void ldsm4(uint32_t* r, uint32_t a) {
    asm volatile("ldmatrix.sync.aligned.m8n8.x4.shared.b16 {%0,%1,%2,%3}, [%4];"
                 : "=r"(r[0]), "=r"(r[1]), "=r"(r[2]), "=r"(r[3]) : "r"(a));
}

__device__ __forceinline__ void mma16816(float* c, const uint32_t* a,
                                         uint32_t b0, uint32_t b1) {
    asm volatile(
        "mma.sync.aligned.m16n8k16.row.col.f32.f16.f16.f32 "
        "{%0,%1,%2,%3}, {%4,%5,%6,%7}, {%8,%9}, {%0,%1,%2,%3};"
        : "+f"(c[0]), "+f"(c[1]), "+f"(c[2]), "+f"(c[3])
        : "r"(a[0]), "r"(a[1]), "r"(a[2]), "r"(a[3]), "r"(b0), "r"(b1));
}

__device__ __forceinline__ float fast_sigmoid(float v) {
    return __fdividef(1.0f, 1.0f + __expf(-v));
}
__device__ __forceinline__ float fast_tanh(float v) {
    float a = fabsf(v);
    float t = __expf(-2.0f * a);
    float r = __fdividef(1.0f - t, 1.0f + t);
    return copysignf(r, v);
}

// smem stage layout (per 48KB stage): A_hi 16K | A_lo 16K | B_hi 8K | B_lo 8K
#define AHI_O 0
#define ALO_O 16384
#define BHI_O 32768
#define BLO_O 40960
#define STAGE_B 49152
#define NSTAGE 3
#define SMEM_TOTAL (NSTAGE * STAGE_B)   // 147456

// ---------------- init: coalesced tiled transpose of Wh into split fp16 -----
__global__ __launch_bounds__(256) void init_w_kernel(const float* __restrict__ Wh) {
    __shared__ float tile[64][65];
    const int cb = blockIdx.x >> 5;        // 0..127  (colp tile /64)
    const int kb = blockIdx.x & 31;        // 0..31   (k tile /64)
    const int tid = threadIdx.x;

    {
        const int k_local = tid >> 2;      // 0..63
        const int seg0 = tid & 3;
        const size_t krow = (size_t)(kb * 64 + k_local) * FOURH;
        #pragma unroll
        for (int ss = 0; ss < 2; ss++) {
            const int s = seg0 + ss * 4;   // 0..7
            const int w_n = s >> 2;
            const int gate = s & 3;
            const int base_o = gate * HID + cb * 16 + w_n * 8;
            const float4 v0 = *(const float4*)(Wh + krow + base_o);
            const float4 v1 = *(const float4*)(Wh + krow + base_o + 4);
            const int r0 = w_n * 32 + gate * 8;
            tile[r0 + 0][k_local] = v0.x;
            tile[r0 + 1][k_local] = v0.y;
            tile[r0 + 2][k_local] = v0.z;
            tile[r0 + 3][k_local] = v0.w;
            tile[r0 + 4][k_local] = v1.x;
            tile[r0 + 5][k_local] = v1.y;
            tile[r0 + 6][k_local] = v1.z;
            tile[r0 + 7][k_local] = v1.w;
        }
    }
    __syncthreads();

    {
        const int r  = tid >> 2;           // 0..63
        const int k0 = (tid & 3) * 16;
        const size_t obase = (size_t)(cb * 64 + r) * HID + kb * 64 + k0;
        __half hibuf[16], lobuf[16];
        #pragma unroll
        for (int i = 0; i < 16; i++) {
            const float v = tile[r][k0 + i];
            const __half hi = __float2half(v);
            hibuf[i] = hi;
            lobuf[i] = __float2half(v - __half2float(hi));
        }
        *(uint4*)(g_W_hi + obase)     = *(uint4*)(hibuf);
        *(uint4*)(g_W_hi + obase + 8) = *(uint4*)(hibuf + 8);
        *(uint4*)(g_W_lo + obase)     = *(uint4*)(lobuf);
        *(uint4*)(g_W_lo + obase + 8) = *(uint4*)(lobuf + 8);
    }
}

__global__ void zero_kernel() {
    const int n = BATCH_ * HID;
    for (int i = blockIdx.x * blockDim.x + threadIdx.x; i < n;
         i += gridDim.x * blockDim.x) {
        g_c[i] = 0.0f;
        g_h_hi[0][i] = __float2half(0.0f);
        g_h_lo[0][i] = __float2half(0.0f);
    }
}

// ---------------- one LSTM timestep ------------------------------------------
__global__ __launch_bounds__(256, 1) void step_kernel(
    const float* __restrict__ x, const float* __restrict__ Wx,
    const float* __restrict__ bvec, int t)
{
    extern __shared__ __align__(1024) unsigned char smem[];
    const uint32_t sb = smem_u32(smem);
    const int tid  = threadIdx.x;
    const int w    = tid >> 5;
    const int lane = tid & 31;
    const int w_m  = w >> 1;          // 0..3 (row group of 32)
    const int w_n  = w & 1;           // 0..1 (col group of 32)
    const int blk  = blockIdx.x;

    const int par0 = t & 1;
    const int par1 = (t + 1) & 1;

    // -------- precomputed cp.async source pointers (per thread) -------------
    const int arow = tid >> 3;
    const int kk   = (tid & 7) * 8;
    const uint32_t aso = sw128((uint32_t)arow * 128 + kk * 2);
    const __half* __restrict__ pAh = g_h_hi[par0] + (size_t)arow * HID + kk;
    const __half* __restrict__ pAl = g_h_lo[par0] + (size_t)arow * HID + kk;
    const __half* __restrict__ pBh = g_W_hi + (size_t)(blk * 64 + arow) * HID + kk;
    const __half* __restrict__ pBl = g_W_lo + (size_t)(blk * 64 + arow) * HID + kk;

    // -------- hoisted epilogue operands (latency hidden under mainloop) -----
    const int q2 = (lane & 3) * 2;
    const int hcol0 = blk * 16 + w_n * 8 + q2;
    float wx[4][2], bb[4][2];
    #pragma unroll
    for (int g = 0; g < 4; g++) {
        const int o = g * HID + hcol0;
        wx[g][0] = Wx[o];     wx[g][1] = Wx[o + 1];
        bb[g][0] = bvec[o];   bb[g][1] = bvec[o + 1];
    }
    const int rbase = w_m * 32 + (lane >> 2);
    float xt[2][2];
    #pragma unroll
    for (int m = 0; m < 2; m++)
        #pragma unroll
        for (int rh = 0; rh < 2; rh++)
            xt[m][rh] = x[(rbase + m * 16 + rh * 8) * TLEN + t];

    // -------- precomputed ldsm swizzled base offsets -------------------------
    // sw128(base + kb) == sw128(base) ^ kb  for 128-aligned base, kb < 128
    const int lm = lane & 15;
    const int lh = lane >> 4;
    const uint32_t kb_lane = (uint32_t)lh * 16;
    uint32_t roAhi[2], roAlo[2], roBhi[2], roBlo[2];
    #pragma unroll
    for (int m = 0; m < 2; m++) {
        const uint32_t s = sw128(((uint32_t)(w_m * 32 + lm) + m * 16) * 128);
        roAhi[m] = (AHI_O + s) ^ kb_lane;
        roAlo[m] = (ALO_O + s) ^ kb_lane;
    }
    #pragma unroll
    for (int g = 0; g < 2; g++) {
        const uint32_t s = sw128(((uint32_t)(w_n * 32 + lm) + g * 16) * 128);
        roBhi[g] = (BHI_O + s) ^ kb_lane;
        roBlo[g] = (BLO_O + s) ^ kb_lane;
    }

    float cacc[2][4][4];
    #pragma unroll
    for (int m = 0; m < 2; m++)
        #pragma unroll
        for (int g = 0; g < 4; g++)
            #pragma unroll
            for (int i = 0; i < 4; i++) cacc[m][g][i] = 0.0f;

    // -------- chunk issue (4+4+2+2 cp.async, precomputed pointers) ----------
    auto issue_chunk = [&](uint32_t st, int c) {
        const int ko = c * BK;
        #pragma unroll
        for (int i = 0; i < 4; i++) {
            cp16(st + AHI_O + aso + i * 4096, pAh + ko + (size_t)i * 32 * HID);
            cp16(st + ALO_O + aso + i * 4096, pAl + ko + (size_t)i * 32 * HID);
        }
        #pragma unroll
        for (int i = 0; i < 2; i++) {
            cp16(st + BHI_O + aso + i * 4096, pBh + ko + (size_t)i * 32 * HID);
            cp16(st + BLO_O + aso + i * 4096, pBl + ko + (size_t)i * 32 * HID);
        }
        asm volatile("cp.async.commit_group;" ::: "memory");
    };

    // prologue: 2 chunks in flight
    issue_chunk(sb, 0);
    issue_chunk(sb + STAGE_B, 1);

    uint32_t stage = 0;     // stage holding chunk c
    uint32_t stage2 = 2;    // stage to fill with chunk c+2
    #pragma unroll 1
    for (int c = 0; c < NCHUNK; c++) {
        if (c < NCHUNK - 1)
            asm volatile("cp.async.wait_group 1;" ::: "memory");
        else
            asm volatile("cp.async.wait_group 0;" ::: "memory");
        __syncthreads();

        if (c + 2 < NCHUNK)
            issue_chunk(sb + stage2 * STAGE_B, c + 2);

        const uint32_t st = sb + stage * STAGE_B;
        #pragma unroll
        for (int ks = 0; ks < 4; ks++) {
            const uint32_t kx = (uint32_t)ks * 32;
            uint32_t ahi[2][4], alo[2][4], bhi[2][4], blo[2][4];
            #pragma unroll
            for (int m = 0; m < 2; m++) {
                ldsm4(ahi[m], st + (roAhi[m] ^ kx));
                ldsm4(alo[m], st + (roAlo[m] ^ kx));
            }
            #pragma unroll
            for (int gg = 0; gg < 2; gg++) {
                ldsm4(bhi[gg], st + (roBhi[gg] ^ kx));
                ldsm4(blo[gg], st + (roBlo[gg] ^ kx));
            }
            #pragma unroll
            for (int m = 0; m < 2; m++) {
                #pragma unroll
                for (int g = 0; g < 4; g++) {
                    const int gg = g >> 1, pr = g & 1;
                    const uint32_t b0h = bhi[gg][pr], b1h = bhi[gg][pr + 2];
                    const uint32_t b0l = blo[gg][pr], b1l = blo[gg][pr + 2];
                    mma16816(cacc[m][g], ahi[m], b0h, b1h);   // hi*hi
                    mma16816(cacc[m][g], ahi[m], b0l, b1l);   // hi*lo
                    mma16816(cacc[m][g], alo[m], b0h, b1h);   // lo*hi
                }
            }
        }
        stage  = (stage == NSTAGE - 1) ? 0 : stage + 1;
        stage2 = (stage2 == NSTAGE - 1) ? 0 : stage2 + 1;
    }

    // ---- fused LSTM epilogue: all 4 gates of (row, hcol) in this thread ----
    #pragma unroll
    for (int m = 0; m < 2; m++) {
        #pragma unroll
        for (int rh = 0; rh < 2; rh++) {
            const int row = rbase + m * 16 + rh * 8;
            const float xv = xt[m][rh];
            const size_t base = (size_t)row * HID + hcol0;
            const float2 cold = *(const float2*)(g_c + base);
            float hv[2], cv[2];
            #pragma unroll
            for (int e = 0; e < 2; e++) {
                const int ri = rh * 2 + e;
                const float zg = cacc[m][0][ri] + xv * wx[0][e] + bb[0][e];
                const float zi = cacc[m][1][ri] + xv * wx[1][e] + bb[1][e];
                const float zf = cacc[m][2][ri] + xv * wx[2][e] + bb[2][e];
                const float zo = cacc[m][3][ri] + xv * wx[3][e] + bb[3][e];
                const float gg = fast_tanh(zg);
                const float ii = fast_sigmoid(zi);
                const float ff = fast_sigmoid(zf);
                const float oo = fast_sigmoid(zo);
                const float co = (e == 0) ? cold.x : cold.y;
                cv[e] = gg * ii + co * ff;
                hv[e] = fast_tanh(cv[e]) * oo;
            }
            *(float2*)(g_c + base) = make_float2(cv[0], cv[1]);
            __half hh0 = __float2half(hv[0]);
            __half hh1 = __float2half(hv[1]);
            __half hl0 = __float2half(hv[0] - __half2float(hh0));
            __half hl1 = __float2half(hv[1] - __half2float(hh1));
            *(__half2*)(g_h_hi[par1] + base) = __halves2half2(hh0, hh1);
            *(__half2*)(g_h_lo[par1] + base) = __halves2half2(hl0, hl1);
        }
    }
}

// ---------------- final projection + softmax ---------------------------------
__global__ void proj_kernel(const float* __restrict__ Wph,
                            const float* __restrict__ bp,
                            float* __restrict__ out)
{
    const int row = blockIdx.x;
    const int lane = threadIdx.x;
    const int par = NSTEP & 1;   // 1

    float acc = -1e30f;
    if (lane < 10) {
        acc = bp[lane];
        const size_t base = (size_t)row * HID;
        for (int k = 0; k < HID; k++) {
            const float hv = __half2float(g_h_hi[par][base + k]) +
                             __half2float(g_h_lo[par][base + k]);
            acc += hv * Wph[k * 10 + lane];
        }
    }
    float m = acc;
    #pragma unroll
    for (int off = 16; off > 0; off >>= 1)
        m = fmaxf(m, __shfl_xor_sync(0xffffffffu, m, off));
    float e = (lane < 10) ? __expf(acc - m) : 0.0f;
    float s = e;
    #pragma unroll
    for (int off = 16; off > 0; off >>= 1)
        s += __shfl_xor_sync(0xffffffffu, s, off);
    if (lane < 10) out[row * 10 + lane] = e / s;
}

extern "C" void kernel_launch(void* const* d_in, const int* in_sizes, int n_in,
                              void* d_out, int out_size) {
    (void)in_sizes; (void)n_in; (void)out_size;
    const float* x   = (const float*)d_in[0];
    const float* Wx  = (const float*)d_in[1];
    const float* Wh  = (const float*)d_in[2];
    const float* b   = (const float*)d_in[3];
    const float* Wph = (const float*)d_in[4];
    const float* bp  = (const float*)d_in[5];
    float* out = (float*)d_out;

    static int attr_set = 0;
    if (!attr_set) {
        cudaFuncSetAttribute(step_kernel,
                             cudaFuncAttributeMaxDynamicSharedMemorySize,
                             SMEM_TOTAL);
        attr_set = 1;
    }

    init_w_kernel<<<4096, 256>>>(Wh);
    zero_kernel<<<256, 256>>>();
    for (int t = 0; t < NSTEP; t++) {
        step_kernel<<<NBLK, 256, SMEM_TOTAL>>>(x, Wx, b, t);
    }
    proj_kernel<<<BATCH_, 32>>>(Wph, bp, out);
}